// round 5
// baseline (speedup 1.0000x reference)
#include <cuda_runtime.h>
#include <cstdint>
#include <math.h>

// ---------------- problem constants ----------------
#define BATCH    2
#define SEQLEN   4096
#define NTOK     8192
#define DMODEL   1024
#define DINNER   2048
#define DSTATE   64
#define NHEADS   32
#define HDIM     64
#define CONVK    4
#define CHUNKSZ  128
#define NCHUNK   32
#define DXBC     6144
#define DPROJ    8224

// ---------------- device scratch (allocation-free) ----------------
__device__ float g_proj[(size_t)NTOK * DPROJ];
__device__ float g_xbc[(size_t)NTOK * DXBC];
__device__ float g_dacum[BATCH * NHEADS * NCHUNK * CHUNKSZ];
__device__ float g_states[(size_t)BATCH * NCHUNK * NHEADS * HDIM * DSTATE];
__device__ float g_prev[(size_t)BATCH * NCHUNK * NHEADS * HDIM * DSTATE];
__device__ float g_yz[(size_t)NTOK * DINNER];

// ================= helpers =================
__device__ __forceinline__ uint32_t smem_u32(const void* p) {
    uint32_t a;
    asm("{ .reg .u64 t; cvta.to.shared.u64 t, %1; cvt.u32.u64 %0, t; }" : "=r"(a) : "l"(p));
    return a;
}
__device__ __forceinline__ void cp_async16(uint32_t s, const void* g) {
    asm volatile("cp.async.cg.shared.global [%0], [%1], 16;" :: "r"(s), "l"(g) : "memory");
}
__device__ __forceinline__ void sts_zero16(uint32_t s) {
    asm volatile("st.shared.v4.b32 [%0], {%1,%1,%1,%1};" :: "r"(s), "r"(0u) : "memory");
}
#define CP_COMMIT() asm volatile("cp.async.commit_group;" ::: "memory")
#define CP_WAIT2()  asm volatile("cp.async.wait_group 2;" ::: "memory")

__device__ __forceinline__ void mma_tf32(float& d0, float& d1, float& d2, float& d3,
                                         uint32_t a0, uint32_t a1, uint32_t a2, uint32_t a3,
                                         uint32_t b0, uint32_t b1) {
    asm volatile(
        "mma.sync.aligned.m16n8k8.row.col.f32.tf32.tf32.f32 "
        "{%0,%1,%2,%3}, {%4,%5,%6,%7}, {%8,%9}, {%0,%1,%2,%3};"
        : "+f"(d0), "+f"(d1), "+f"(d2), "+f"(d3)
        : "r"(a0), "r"(a1), "r"(a2), "r"(a3), "r"(b0), "r"(b1));
}

// ================= TF32 mma.sync GEMM (NT): C[m,n] = sum_k A[m,k]B[n,k] =================
// Block 128x256, 8 warps (2x4), warp tile 64x64, k-tile 16, 4-stage single-barrier
// cp.async pipeline. RNA rounding fused into fragment loads (+0x1000, HW truncates).
#define KTILE   16
#define NSTAGE  4
#define TSTRIDE 20                              // floats per smem row (16 + 4 pad)
#define A_FLOATS (128 * TSTRIDE)                // 2560
#define B_FLOATS (256 * TSTRIDE)                // 5120
#define GSTAGE_FLOATS (A_FLOATS + B_FLOATS)     // 7680
#define SMEM_GEMM (NSTAGE * GSTAGE_FLOATS * 4)  // 122880 bytes

__device__ __forceinline__ void load_tile_mma(const float* __restrict__ A,
                                              const float* __restrict__ B,
                                              int K, int Nn, int bm, int bn,
                                              int ti, uint32_t sb, int tid)
{
    uint32_t st = sb + (uint32_t)(ti & (NSTAGE - 1)) * (GSTAGE_FLOATS * 4);
    const float* ag = A + (size_t)bm * K + (size_t)ti * KTILE;
#pragma unroll
    for (int i = 0; i < 2; i++) {                 // A: 128 rows x 4 chunks = 512
        int flat = tid + (i << 8);
        int r = flat >> 2, c = flat & 3;
        cp_async16(st + r * (TSTRIDE * 4) + c * 16, ag + (size_t)r * K + c * 4);
    }
    uint32_t stb = st + A_FLOATS * 4;
    const float* bg = B + (size_t)ti * KTILE;
#pragma unroll
    for (int i = 0; i < 4; i++) {                 // B: 256 rows x 4 chunks = 1024
        int flat = tid + (i << 8);
        int r = flat >> 2, c = flat & 3;
        uint32_t so = stb + r * (TSTRIDE * 4) + c * 16;
        int gn = bn + r;
        if (gn < Nn) cp_async16(so, bg + (size_t)gn * K + c * 4);
        else         sts_zero16(so);
    }
}

__global__ void __launch_bounds__(256, 1)
gemm_mma(const float* __restrict__ A, const float* __restrict__ B,
         float* __restrict__ C, int M, int Nn, int K)
{
    extern __shared__ float dsm[];
    const int tid = threadIdx.x;
    const int wid = tid >> 5;
    const int lane = tid & 31;
    const int g = lane >> 2;                     // 0..7
    const int q = lane & 3;                      // 0..3
    const int wm = (wid & 1) * 64;               // warp M offset
    const int wn = (wid >> 1) * 64;              // warp N offset
    const int KT = K / KTILE;
    const int bm = blockIdx.y << 7;
    const int bn = blockIdx.x << 8;
    uint32_t sb = smem_u32(dsm);

    float acc[4][8][4];
#pragma unroll
    for (int mi = 0; mi < 4; mi++)
#pragma unroll
        for (int ni = 0; ni < 8; ni++)
#pragma unroll
            for (int e = 0; e < 4; e++) acc[mi][ni][e] = 0.f;

    // prologue: tiles 0..2
#pragma unroll
    for (int t = 0; t < 3; t++) {
        load_tile_mma(A, B, K, Nn, bm, bn, t, sb, tid);
        CP_COMMIT();
    }

    for (int kt = 0; kt < KT; kt++) {
        CP_WAIT2();                 // tile kt resident (pending kt..kt+2 at top)
        __syncthreads();            // visibility + WAR cover (single barrier/iter)
        int ld = kt + 3;
        if (ld < KT) load_tile_mma(A, B, K, Nn, bm, bn, ld, sb, tid);
        CP_COMMIT();

        const float* As = dsm + (kt & (NSTAGE - 1)) * GSTAGE_FLOATS;
        const float* Bs = As + A_FLOATS;
#pragma unroll
        for (int ks = 0; ks < 2; ks++) {
            int k0 = ks * 8;
            uint32_t a[4][4];
#pragma unroll
            for (int mi = 0; mi < 4; mi++) {
                int row = wm + mi * 16;
                a[mi][0] = __float_as_uint(As[(row + g)     * TSTRIDE + k0 + q])     + 0x1000u;
                a[mi][1] = __float_as_uint(As[(row + g + 8) * TSTRIDE + k0 + q])     + 0x1000u;
                a[mi][2] = __float_as_uint(As[(row + g)     * TSTRIDE + k0 + q + 4]) + 0x1000u;
                a[mi][3] = __float_as_uint(As[(row + g + 8) * TSTRIDE + k0 + q + 4]) + 0x1000u;
            }
            uint32_t b[8][2];
#pragma unroll
            for (int ni = 0; ni < 8; ni++) {
                int col = wn + ni * 8;
                b[ni][0] = __float_as_uint(Bs[(col + g) * TSTRIDE + k0 + q])     + 0x1000u;
                b[ni][1] = __float_as_uint(Bs[(col + g) * TSTRIDE + k0 + q + 4]) + 0x1000u;
            }
#pragma unroll
            for (int mi = 0; mi < 4; mi++)
#pragma unroll
                for (int ni = 0; ni < 8; ni++)
                    mma_tf32(acc[mi][ni][0], acc[mi][ni][1], acc[mi][ni][2], acc[mi][ni][3],
                             a[mi][0], a[mi][1], a[mi][2], a[mi][3],
                             b[ni][0], b[ni][1]);
        }
    }

    // epilogue: registers -> gmem
#pragma unroll
    for (int mi = 0; mi < 4; mi++) {
#pragma unroll
        for (int ni = 0; ni < 8; ni++) {
            int col = bn + wn + ni * 8 + 2 * q;
            if (col < Nn) {
                int r0 = bm + wm + mi * 16 + g;
                *(float2*)(C + (size_t)r0 * Nn + col) =
                    make_float2(acc[mi][ni][0], acc[mi][ni][1]);
                *(float2*)(C + (size_t)(r0 + 8) * Nn + col) =
                    make_float2(acc[mi][ni][2], acc[mi][ni][3]);
            }
        }
    }
}

// ================= conv + silu (register-rolling window, 16 t/thread) =================
__global__ void __launch_bounds__(256) conv_silu_kernel(const float* __restrict__ cw,
                                                        const float* __restrict__ cb)
{
    int ch = blockIdx.x * 256 + threadIdx.x;
    int tb = blockIdx.y * 16;
    int b = tb >> 12;
    int l0 = tb & (SEQLEN - 1);
    float c0 = cw[ch * 4 + 0], c1 = cw[ch * 4 + 1], c2 = cw[ch * 4 + 2], c3 = cw[ch * 4 + 3];
    float bias = cb[ch];
    const float* base = g_proj + (size_t)(b * SEQLEN) * DPROJ + ch;
    float* outb = g_xbc + (size_t)(b * SEQLEN) * DXBC + ch;
    float w0 = (l0 >= 3) ? base[(size_t)(l0 - 3) * DPROJ] : 0.f;
    float w1 = (l0 >= 2) ? base[(size_t)(l0 - 2) * DPROJ] : 0.f;
    float w2 = (l0 >= 1) ? base[(size_t)(l0 - 1) * DPROJ] : 0.f;
#pragma unroll
    for (int tt = 0; tt < 16; tt++) {
        float xv = base[(size_t)(l0 + tt) * DPROJ];
        float a = fmaf(c3, xv, fmaf(c2, w2, fmaf(c1, w1, fmaf(c0, w0, bias))));
        outb[(size_t)(l0 + tt) * DXBC] = a / (1.f + expf(-a));
        w0 = w1; w1 = w2; w2 = xv;
    }
}

// ================= dA cumsum: one warp per (b,h,c) =================
__global__ void __launch_bounds__(256) dacum_kernel()
{
    int gw = (blockIdx.x * blockDim.x + threadIdx.x) >> 5;
    int lane = threadIdx.x & 31;
    if (gw >= BATCH * NHEADS * NCHUNK) return;
    int c = gw & 31, h = (gw >> 5) & 31, b = gw >> 10;
    int t0 = b * SEQLEN + c * CHUNKSZ + lane * 4;
    float p[4], run = 0.f;
#pragma unroll
    for (int j = 0; j < 4; j++) {
        float v = g_proj[(size_t)(t0 + j) * DPROJ + (DXBC + DINNER) + h];
        run += fmaxf(v, 0.f) + log1pf(expf(-fabsf(v)));
        p[j] = run;
    }
    float tot = run;
#pragma unroll
    for (int off = 1; off < 32; off <<= 1) {
        float nb = __shfl_up_sync(0xFFFFFFFFu, tot, off);
        if (lane >= off) tot += nb;
    }
    float excl = tot - run;
    int ob = ((b * 32 + h) * 32 + c) * CHUNKSZ + lane * 4;
#pragma unroll
    for (int j = 0; j < 4; j++) g_dacum[ob + j] = -(excl + p[j]);
}

// ================= chunk states =================
#define SMEM_STATES ((2 * 128 * 65 + 128) * 4)
__global__ void __launch_bounds__(256, 1) states_kernel()
{
    extern __shared__ float sm[];
    float* Bs = sm;
    float* xs = sm + 128 * 65;
    float* da = xs + 128 * 65;

    int bi = blockIdx.x;
    int h = bi & 31, c = (bi >> 5) & 31, b = bi >> 10;
    int tid = threadIdx.x;
    int base_t = b * SEQLEN + c * CHUNKSZ;
    int dab = ((b * 32 + h) * 32 + c) * CHUNKSZ;

    if (tid < 128) da[tid] = g_dacum[dab + tid];
    __syncthreads();
    float da_last = da[127];

#pragma unroll
    for (int i = 0; i < 32; i++) {
        int flat = tid + 256 * i;
        int s = flat >> 6, p = flat & 63;
        size_t goff = (size_t)(base_t + s) * DXBC + h * 64 + p;
        float dec = __expf(da_last - da[s]);
        xs[s * 65 + p] = g_xbc[goff] * dec;
        Bs[s * 65 + p] = g_xbc[goff + DINNER];
    }
    __syncthreads();

    int n = tid & 63, pg = tid >> 6;
    float acc[16];
#pragma unroll
    for (int i = 0; i < 16; i++) acc[i] = 0.f;
    for (int s = 0; s < CHUNKSZ; s++) {
        float bv = Bs[s * 65 + n];
#pragma unroll
        for (int i = 0; i < 16; i++)
            acc[i] = fmaf(bv, xs[s * 65 + pg + 4 * i], acc[i]);
    }
    size_t sbo = (size_t)((b * 32 + c) * 32 + h) * (HDIM * DSTATE);
#pragma unroll
    for (int i = 0; i < 16; i++)
        g_states[sbo + (pg + 4 * i) * 64 + n] = acc[i];
}

// ================= inter-chunk scan =================
__global__ void __launch_bounds__(256) scan_kernel()
{
    int bi = blockIdx.x;               // (b*32+h)*16 + q
    int q = bi & 15;
    int bh = bi >> 4;
    int b = bh >> 5, h = bh & 31;
    int e = q * 256 + threadIdx.x;
    float carry = 0.f;
    for (int c = 0; c < NCHUNK; c++) {
        size_t sbo = (size_t)((b * 32 + c) * 32 + h) * (HDIM * DSTATE);
        float dec = expf(g_dacum[((b * 32 + h) * 32 + c) * CHUNKSZ + 127]);
        g_prev[sbo + e] = carry;
        carry = fmaf(carry, dec, g_states[sbo + e]);
    }
}

// ================= fused Y kernel =================
#define SMEM_Y ((3 * 128 * 65 + 128 * 129 + 64 * 65 + 128) * 4)
__global__ void __launch_bounds__(256, 1) y_kernel(const float* __restrict__ zb,
                                                   const float* __restrict__ Dp)
{
    extern __shared__ float sm[];
    float* Cs = sm;
    float* Bs = Cs + 128 * 65;
    float* xs = Bs + 128 * 65;
    float* G  = xs + 128 * 65;
    float* pT = G + 128 * 129;
    float* da = pT + 64 * 65;

    int bi = blockIdx.x;
    int h = bi & 31, c = (bi >> 5) & 31, b = bi >> 10;
    int tid = threadIdx.x;
    int base_t = b * SEQLEN + c * CHUNKSZ;
    int dab = ((b * 32 + h) * 32 + c) * CHUNKSZ;
    size_t pb = (size_t)((b * 32 + c) * 32 + h) * (HDIM * DSTATE);

    if (tid < 128) da[tid] = g_dacum[dab + tid];
#pragma unroll
    for (int i = 0; i < 32; i++) {
        int flat = tid + 256 * i;
        int s = flat >> 6, p = flat & 63;
        size_t goff = (size_t)(base_t + s) * DXBC + h * 64 + p;
        xs[s * 65 + p] = g_xbc[goff];
        Bs[s * 65 + p] = g_xbc[goff + DINNER];
        Cs[s * 65 + p] = g_xbc[goff + 2 * DINNER];
    }
#pragma unroll
    for (int i = 0; i < 16; i++) {
        int flat = tid + 256 * i;
        int p = flat >> 6, n = flat & 63;
        pT[n * 65 + p] = g_prev[pb + flat];
    }
    __syncthreads();

    {
        int tr = tid >> 4, tc = tid & 15;
        float accg[8][8];
#pragma unroll
        for (int i = 0; i < 8; i++)
#pragma unroll
            for (int j = 0; j < 8; j++) accg[i][j] = 0.f;
        for (int n = 0; n < DSTATE; n++) {
            float a[8], bb[8];
#pragma unroll
            for (int i = 0; i < 8; i++) a[i] = Cs[(tr + 16 * i) * 65 + n];
#pragma unroll
            for (int j = 0; j < 8; j++) bb[j] = Bs[(tc + 16 * j) * 65 + n];
#pragma unroll
            for (int i = 0; i < 8; i++)
#pragma unroll
                for (int j = 0; j < 8; j++)
                    accg[i][j] = fmaf(a[i], bb[j], accg[i][j]);
        }
#pragma unroll
        for (int i = 0; i < 8; i++) {
            int l = tr + 16 * i;
            float dal = da[l];
#pragma unroll
            for (int j = 0; j < 8; j++) {
                int s = tc + 16 * j;
                G[l * 129 + s] = (s <= l) ? accg[i][j] * __expf(dal - da[s]) : 0.f;
            }
        }
    }
    __syncthreads();

    {
        int p = tid & 63;
        int tr2 = tid >> 6;
        float acc[32], acc2[32];
#pragma unroll
        for (int i = 0; i < 32; i++) { acc[i] = 0.f; acc2[i] = 0.f; }

        for (int s = 0; s < CHUNKSZ; s++) {
            float xv = xs[s * 65 + p];
#pragma unroll
            for (int i = 0; i < 32; i++)
                acc[i] = fmaf(G[(tr2 + 4 * i) * 129 + s], xv, acc[i]);
        }
        for (int n = 0; n < DSTATE; n++) {
            float pv = pT[n * 65 + p];
#pragma unroll
            for (int i = 0; i < 32; i++)
                acc2[i] = fmaf(Cs[(tr2 + 4 * i) * 65 + n], pv, acc2[i]);
        }

        float Dh = Dp[h];
        int chn = h * 64 + p;
        float zbias = zb[chn];
#pragma unroll
        for (int i = 0; i < 32; i++) {
            int l = tr2 + 4 * i;
            int t = base_t + l;
            float yv = acc[i] + __expf(da[l]) * acc2[i] + Dh * xs[l * 65 + p];
            float zv = g_proj[(size_t)t * DPROJ + DXBC + chn] + zbias;
            float sil = zv / (1.f + expf(-zv));
            g_yz[(size_t)t * DINNER + chn] = yv * sil;
        }
    }
}

// ================= launch =================
extern "C" void kernel_launch(void* const* d_in, const int* in_sizes, int n_in,
                              void* d_out, int out_size)
{
    const float* u          = (const float*)d_in[0];
    const float* in_proj_w  = (const float*)d_in[1];
    const float* z_bias     = (const float*)d_in[2];
    const float* conv_w     = (const float*)d_in[3];
    const float* conv_b     = (const float*)d_in[4];
    const float* Dparam     = (const float*)d_in[5];
    const float* out_proj_w = (const float*)d_in[6];
    float* out = (float*)d_out;

    void *p_proj = nullptr, *p_yz = nullptr;
    cudaGetSymbolAddress(&p_proj, g_proj);
    cudaGetSymbolAddress(&p_yz, g_yz);

    cudaFuncSetAttribute(gemm_mma, cudaFuncAttributeMaxDynamicSharedMemorySize, SMEM_GEMM);
    cudaFuncSetAttribute(states_kernel, cudaFuncAttributeMaxDynamicSharedMemorySize, SMEM_STATES);
    cudaFuncSetAttribute(y_kernel, cudaFuncAttributeMaxDynamicSharedMemorySize, SMEM_Y);

    // 1) in_proj GEMM (tf32 mma.sync, fused RNA round): [8192,1024] x [8224,1024]^T
    {
        dim3 grid((DPROJ + 255) / 256, NTOK / 128);
        gemm_mma<<<grid, 256, SMEM_GEMM>>>(u, in_proj_w, (float*)p_proj, NTOK, DPROJ, DMODEL);
    }
    // 2) conv + silu
    {
        dim3 grid(DXBC / 256, NTOK / 16);
        conv_silu_kernel<<<grid, 256>>>(conv_w, conv_b);
    }
    // 3) dA cumsum
    dacum_kernel<<<(BATCH * NHEADS * NCHUNK * 32 + 255) / 256, 256>>>();
    // 4) chunk states
    states_kernel<<<BATCH * NCHUNK * NHEADS, 256, SMEM_STATES>>>();
    // 5) inter-chunk scan
    scan_kernel<<<BATCH * NHEADS * 16, 256>>>();
    // 6) fused Y + gating
    y_kernel<<<BATCH * NCHUNK * NHEADS, 256, SMEM_Y>>>(z_bias, Dparam);
    // 7) out_proj GEMM (tf32 mma.sync, fused RNA round): [8192,2048] x [1024,2048]^T
    {
        dim3 grid(DMODEL / 256, NTOK / 128);
        gemm_mma<<<grid, 256, SMEM_GEMM>>>((const float*)p_yz, out_proj_w, out, NTOK, DMODEL, DINNER);
    }
}

// round 6
// speedup vs baseline: 1.3674x; 1.3674x over previous
#include <cuda_runtime.h>
#include <cuda_fp16.h>
#include <cstdint>
#include <math.h>

// ---------------- problem constants ----------------
#define BATCH    2
#define SEQLEN   4096
#define NTOK     8192
#define DMODEL   1024
#define DINNER   2048
#define DSTATE   64
#define NHEADS   32
#define HDIM     64
#define CONVK    4
#define CHUNKSZ  128
#define NCHUNK   32
#define DXBC     6144
#define DPROJ    8224

// ---------------- device scratch (allocation-free) ----------------
__device__ float  g_proj[(size_t)NTOK * DPROJ];
__device__ float  g_xbc[(size_t)NTOK * DXBC];
__device__ float  g_dacum[BATCH * NHEADS * NCHUNK * CHUNKSZ];
__device__ float  g_states[(size_t)BATCH * NCHUNK * NHEADS * HDIM * DSTATE];
__device__ float  g_prev[(size_t)BATCH * NCHUNK * NHEADS * HDIM * DSTATE];
__device__ __half g_yz16[(size_t)NTOK * DINNER];
__device__ __half g_ua16[(size_t)NTOK * DMODEL];
__device__ __half g_wa16[(size_t)DPROJ * DMODEL];
__device__ __half g_wo16[(size_t)DMODEL * DINNER];

// ================= helpers =================
__device__ __forceinline__ uint32_t smem_u32(const void* p) {
    uint32_t a;
    asm("{ .reg .u64 t; cvta.to.shared.u64 t, %1; cvt.u32.u64 %0, t; }" : "=r"(a) : "l"(p));
    return a;
}
__device__ __forceinline__ void cp_async16(uint32_t s, const void* g) {
    asm volatile("cp.async.cg.shared.global [%0], [%1], 16;" :: "r"(s), "l"(g) : "memory");
}
__device__ __forceinline__ void sts_zero16(uint32_t s) {
    asm volatile("st.shared.v4.b32 [%0], {%1,%1,%1,%1};" :: "r"(s), "r"(0u) : "memory");
}
#define CP_COMMIT() asm volatile("cp.async.commit_group;" ::: "memory")
#define CP_WAIT2()  asm volatile("cp.async.wait_group 2;" ::: "memory")

__device__ __forceinline__ void mma_fp16(float& d0, float& d1, float& d2, float& d3,
                                         uint32_t a0, uint32_t a1, uint32_t a2, uint32_t a3,
                                         uint32_t b0, uint32_t b1) {
    asm volatile(
        "mma.sync.aligned.m16n8k16.row.col.f32.f16.f16.f32 "
        "{%0,%1,%2,%3}, {%4,%5,%6,%7}, {%8,%9}, {%0,%1,%2,%3};"
        : "+f"(d0), "+f"(d1), "+f"(d2), "+f"(d3)
        : "r"(a0), "r"(a1), "r"(a2), "r"(a3), "r"(b0), "r"(b1));
}

// ================= f32 -> f16 conversion =================
__global__ void f2h_kernel(const float* __restrict__ in, __half* __restrict__ out, int n2) {
    int i = blockIdx.x * blockDim.x + threadIdx.x;
    if (i >= n2) return;
    float2 v = ((const float2*)in)[i];
    ((__half2*)out)[i] = __floats2half2_rn(v.x, v.y);
}

// ================= FP16 mma.sync GEMM (NT): C[m,n] = sum_k A[m,k]B[n,k] =================
// A,B fp16 row-major; C fp32. Block 128x256, 8 warps (2x4), warp tile 64x64,
// k-tile 32 halves, 4-stage single-barrier cp.async pipeline.
#define KTILE    32                              // halves per k-tile
#define NSTAGE   4
#define TSTRIDE_H 40                             // halves per smem row (32 + 8 pad) = 80B
#define A_HALVES (128 * TSTRIDE_H)               // 5120
#define B_HALVES (256 * TSTRIDE_H)               // 10240
#define GSTAGE_HALVES (A_HALVES + B_HALVES)      // 15360
#define SMEM_GEMM (NSTAGE * GSTAGE_HALVES * 2)   // 122880 bytes

__device__ __forceinline__ void load_tile_h(const __half* __restrict__ A,
                                            const __half* __restrict__ B,
                                            int K, int Nn, int bm, int bn,
                                            int ti, uint32_t sb, int tid)
{
    uint32_t st = sb + (uint32_t)(ti & (NSTAGE - 1)) * (GSTAGE_HALVES * 2);
    const __half* ag = A + (size_t)bm * K + (size_t)ti * KTILE;
#pragma unroll
    for (int i = 0; i < 2; i++) {                 // A: 128 rows x 4 chunks of 16B
        int flat = tid + (i << 8);
        int r = flat >> 2, c = flat & 3;
        cp_async16(st + r * (TSTRIDE_H * 2) + c * 16, ag + (size_t)r * K + c * 8);
    }
    uint32_t stb = st + A_HALVES * 2;
    const __half* bg = B + (size_t)ti * KTILE;
#pragma unroll
    for (int i = 0; i < 4; i++) {                 // B: 256 rows x 4 chunks of 16B
        int flat = tid + (i << 8);
        int r = flat >> 2, c = flat & 3;
        uint32_t so = stb + r * (TSTRIDE_H * 2) + c * 16;
        int gn = bn + r;
        if (gn < Nn) cp_async16(so, bg + (size_t)gn * K + c * 8);
        else         sts_zero16(so);
    }
}

__global__ void __launch_bounds__(256, 1)
gemm_h(const __half* __restrict__ A, const __half* __restrict__ B,
       float* __restrict__ C, int M, int Nn, int K)
{
    extern __shared__ __align__(16) uint32_t dsm32[];   // half2 view, row stride 20 u32
    const int tid = threadIdx.x;
    const int wid = tid >> 5;
    const int lane = tid & 31;
    const int g = lane >> 2;                     // 0..7
    const int q = lane & 3;                      // 0..3
    const int wm = (wid & 1) * 64;
    const int wn = (wid >> 1) * 64;
    const int KT = K / KTILE;
    const int bm = blockIdx.y << 7;
    const int bn = blockIdx.x << 8;
    uint32_t sb = smem_u32(dsm32);

    float acc[4][8][4];
#pragma unroll
    for (int mi = 0; mi < 4; mi++)
#pragma unroll
        for (int ni = 0; ni < 8; ni++)
#pragma unroll
            for (int e = 0; e < 4; e++) acc[mi][ni][e] = 0.f;

#pragma unroll
    for (int t = 0; t < 3; t++) {
        load_tile_h(A, B, K, Nn, bm, bn, t, sb, tid);
        CP_COMMIT();
    }

    for (int kt = 0; kt < KT; kt++) {
        CP_WAIT2();
        __syncthreads();
        int ld = kt + 3;
        if (ld < KT) load_tile_h(A, B, K, Nn, bm, bn, ld, sb, tid);
        CP_COMMIT();

        const uint32_t* As = dsm32 + (kt & (NSTAGE - 1)) * (GSTAGE_HALVES / 2);
        const uint32_t* Bs = As + A_HALVES / 2;
#pragma unroll
        for (int ks = 0; ks < 2; ks++) {          // two k=16 steps
            int kq = ks * 8 + q;                  // half2 column index
            uint32_t a[4][4];
#pragma unroll
            for (int mi = 0; mi < 4; mi++) {
                int row = wm + mi * 16;
                a[mi][0] = As[(row + g)     * 20 + kq];
                a[mi][1] = As[(row + g + 8) * 20 + kq];
                a[mi][2] = As[(row + g)     * 20 + kq + 4];
                a[mi][3] = As[(row + g + 8) * 20 + kq + 4];
            }
            uint32_t b[8][2];
#pragma unroll
            for (int ni = 0; ni < 8; ni++) {
                int col = wn + ni * 8;
                b[ni][0] = Bs[(col + g) * 20 + kq];
                b[ni][1] = Bs[(col + g) * 20 + kq + 4];
            }
#pragma unroll
            for (int mi = 0; mi < 4; mi++)
#pragma unroll
                for (int ni = 0; ni < 8; ni++)
                    mma_fp16(acc[mi][ni][0], acc[mi][ni][1], acc[mi][ni][2], acc[mi][ni][3],
                             a[mi][0], a[mi][1], a[mi][2], a[mi][3],
                             b[ni][0], b[ni][1]);
        }
    }

    // epilogue: registers -> gmem (fp32)
#pragma unroll
    for (int mi = 0; mi < 4; mi++) {
#pragma unroll
        for (int ni = 0; ni < 8; ni++) {
            int col = bn + wn + ni * 8 + 2 * q;
            if (col < Nn) {
                int r0 = bm + wm + mi * 16 + g;
                *(float2*)(C + (size_t)r0 * Nn + col) =
                    make_float2(acc[mi][ni][0], acc[mi][ni][1]);
                *(float2*)(C + (size_t)(r0 + 8) * Nn + col) =
                    make_float2(acc[mi][ni][2], acc[mi][ni][3]);
            }
        }
    }
}

// ================= conv + silu (register-rolling window, 16 t/thread) =================
__global__ void __launch_bounds__(256) conv_silu_kernel(const float* __restrict__ cw,
                                                        const float* __restrict__ cb)
{
    int ch = blockIdx.x * 256 + threadIdx.x;
    int tb = blockIdx.y * 16;
    int b = tb >> 12;
    int l0 = tb & (SEQLEN - 1);
    float c0 = cw[ch * 4 + 0], c1 = cw[ch * 4 + 1], c2 = cw[ch * 4 + 2], c3 = cw[ch * 4 + 3];
    float bias = cb[ch];
    const float* base = g_proj + (size_t)(b * SEQLEN) * DPROJ + ch;
    float* outb = g_xbc + (size_t)(b * SEQLEN) * DXBC + ch;
    float w0 = (l0 >= 3) ? base[(size_t)(l0 - 3) * DPROJ] : 0.f;
    float w1 = (l0 >= 2) ? base[(size_t)(l0 - 2) * DPROJ] : 0.f;
    float w2 = (l0 >= 1) ? base[(size_t)(l0 - 1) * DPROJ] : 0.f;
#pragma unroll
    for (int tt = 0; tt < 16; tt++) {
        float xv = base[(size_t)(l0 + tt) * DPROJ];
        float a = fmaf(c3, xv, fmaf(c2, w2, fmaf(c1, w1, fmaf(c0, w0, bias))));
        outb[(size_t)(l0 + tt) * DXBC] = a / (1.f + expf(-a));
        w0 = w1; w1 = w2; w2 = xv;
    }
}

// ================= dA cumsum: one warp per (b,h,c) =================
__global__ void __launch_bounds__(256) dacum_kernel()
{
    int gw = (blockIdx.x * blockDim.x + threadIdx.x) >> 5;
    int lane = threadIdx.x & 31;
    if (gw >= BATCH * NHEADS * NCHUNK) return;
    int c = gw & 31, h = (gw >> 5) & 31, b = gw >> 10;
    int t0 = b * SEQLEN + c * CHUNKSZ + lane * 4;
    float p[4], run = 0.f;
#pragma unroll
    for (int j = 0; j < 4; j++) {
        float v = g_proj[(size_t)(t0 + j) * DPROJ + (DXBC + DINNER) + h];
        run += fmaxf(v, 0.f) + log1pf(expf(-fabsf(v)));
        p[j] = run;
    }
    float tot = run;
#pragma unroll
    for (int off = 1; off < 32; off <<= 1) {
        float nb = __shfl_up_sync(0xFFFFFFFFu, tot, off);
        if (lane >= off) tot += nb;
    }
    float excl = tot - run;
    int ob = ((b * 32 + h) * 32 + c) * CHUNKSZ + lane * 4;
#pragma unroll
    for (int j = 0; j < 4; j++) g_dacum[ob + j] = -(excl + p[j]);
}

// ================= chunk states =================
#define SMEM_STATES ((2 * 128 * 65 + 128) * 4)
__global__ void __launch_bounds__(256, 1) states_kernel()
{
    extern __shared__ float sm[];
    float* Bs = sm;
    float* xs = sm + 128 * 65;
    float* da = xs + 128 * 65;

    int bi = blockIdx.x;
    int h = bi & 31, c = (bi >> 5) & 31, b = bi >> 10;
    int tid = threadIdx.x;
    int base_t = b * SEQLEN + c * CHUNKSZ;
    int dab = ((b * 32 + h) * 32 + c) * CHUNKSZ;

    if (tid < 128) da[tid] = g_dacum[dab + tid];
    __syncthreads();
    float da_last = da[127];

#pragma unroll
    for (int i = 0; i < 32; i++) {
        int flat = tid + 256 * i;
        int s = flat >> 6, p = flat & 63;
        size_t goff = (size_t)(base_t + s) * DXBC + h * 64 + p;
        float dec = __expf(da_last - da[s]);
        xs[s * 65 + p] = g_xbc[goff] * dec;
        Bs[s * 65 + p] = g_xbc[goff + DINNER];
    }
    __syncthreads();

    int n = tid & 63, pg = tid >> 6;
    float acc[16];
#pragma unroll
    for (int i = 0; i < 16; i++) acc[i] = 0.f;
    for (int s = 0; s < CHUNKSZ; s++) {
        float bv = Bs[s * 65 + n];
#pragma unroll
        for (int i = 0; i < 16; i++)
            acc[i] = fmaf(bv, xs[s * 65 + pg + 4 * i], acc[i]);
    }
    size_t sbo = (size_t)((b * 32 + c) * 32 + h) * (HDIM * DSTATE);
#pragma unroll
    for (int i = 0; i < 16; i++)
        g_states[sbo + (pg + 4 * i) * 64 + n] = acc[i];
}

// ================= inter-chunk scan =================
__global__ void __launch_bounds__(256) scan_kernel()
{
    int bi = blockIdx.x;
    int q = bi & 15;
    int bh = bi >> 4;
    int b = bh >> 5, h = bh & 31;
    int e = q * 256 + threadIdx.x;
    float carry = 0.f;
    for (int c = 0; c < NCHUNK; c++) {
        size_t sbo = (size_t)((b * 32 + c) * 32 + h) * (HDIM * DSTATE);
        float dec = expf(g_dacum[((b * 32 + h) * 32 + c) * CHUNKSZ + 127]);
        g_prev[sbo + e] = carry;
        carry = fmaf(carry, dec, g_states[sbo + e]);
    }
}

// ================= fused Y kernel (writes fp16 yz) =================
#define SMEM_Y ((3 * 128 * 65 + 128 * 129 + 64 * 65 + 128) * 4)
__global__ void __launch_bounds__(256, 1) y_kernel(const float* __restrict__ zb,
                                                   const float* __restrict__ Dp)
{
    extern __shared__ float sm[];
    float* Cs = sm;
    float* Bs = Cs + 128 * 65;
    float* xs = Bs + 128 * 65;
    float* G  = xs + 128 * 65;
    float* pT = G + 128 * 129;
    float* da = pT + 64 * 65;

    int bi = blockIdx.x;
    int h = bi & 31, c = (bi >> 5) & 31, b = bi >> 10;
    int tid = threadIdx.x;
    int base_t = b * SEQLEN + c * CHUNKSZ;
    int dab = ((b * 32 + h) * 32 + c) * CHUNKSZ;
    size_t pb = (size_t)((b * 32 + c) * 32 + h) * (HDIM * DSTATE);

    if (tid < 128) da[tid] = g_dacum[dab + tid];
#pragma unroll
    for (int i = 0; i < 32; i++) {
        int flat = tid + 256 * i;
        int s = flat >> 6, p = flat & 63;
        size_t goff = (size_t)(base_t + s) * DXBC + h * 64 + p;
        xs[s * 65 + p] = g_xbc[goff];
        Bs[s * 65 + p] = g_xbc[goff + DINNER];
        Cs[s * 65 + p] = g_xbc[goff + 2 * DINNER];
    }
#pragma unroll
    for (int i = 0; i < 16; i++) {
        int flat = tid + 256 * i;
        int p = flat >> 6, n = flat & 63;
        pT[n * 65 + p] = g_prev[pb + flat];
    }
    __syncthreads();

    {
        int tr = tid >> 4, tc = tid & 15;
        float accg[8][8];
#pragma unroll
        for (int i = 0; i < 8; i++)
#pragma unroll
            for (int j = 0; j < 8; j++) accg[i][j] = 0.f;
        for (int n = 0; n < DSTATE; n++) {
            float a[8], bb[8];
#pragma unroll
            for (int i = 0; i < 8; i++) a[i] = Cs[(tr + 16 * i) * 65 + n];
#pragma unroll
            for (int j = 0; j < 8; j++) bb[j] = Bs[(tc + 16 * j) * 65 + n];
#pragma unroll
            for (int i = 0; i < 8; i++)
#pragma unroll
                for (int j = 0; j < 8; j++)
                    accg[i][j] = fmaf(a[i], bb[j], accg[i][j]);
        }
#pragma unroll
        for (int i = 0; i < 8; i++) {
            int l = tr + 16 * i;
            float dal = da[l];
#pragma unroll
            for (int j = 0; j < 8; j++) {
                int s = tc + 16 * j;
                G[l * 129 + s] = (s <= l) ? accg[i][j] * __expf(dal - da[s]) : 0.f;
            }
        }
    }
    __syncthreads();

    {
        int p = tid & 63;
        int tr2 = tid >> 6;
        float acc[32], acc2[32];
#pragma unroll
        for (int i = 0; i < 32; i++) { acc[i] = 0.f; acc2[i] = 0.f; }

        for (int s = 0; s < CHUNKSZ; s++) {
            float xv = xs[s * 65 + p];
#pragma unroll
            for (int i = 0; i < 32; i++)
                acc[i] = fmaf(G[(tr2 + 4 * i) * 129 + s], xv, acc[i]);
        }
        for (int n = 0; n < DSTATE; n++) {
            float pv = pT[n * 65 + p];
#pragma unroll
            for (int i = 0; i < 32; i++)
                acc2[i] = fmaf(Cs[(tr2 + 4 * i) * 65 + n], pv, acc2[i]);
        }

        float Dh = Dp[h];
        int chn = h * 64 + p;
        float zbias = zb[chn];
#pragma unroll
        for (int i = 0; i < 32; i++) {
            int l = tr2 + 4 * i;
            int t = base_t + l;
            float yv = acc[i] + __expf(da[l]) * acc2[i] + Dh * xs[l * 65 + p];
            float zv = g_proj[(size_t)t * DPROJ + DXBC + chn] + zbias;
            float sil = zv / (1.f + expf(-zv));
            g_yz16[(size_t)t * DINNER + chn] = __float2half_rn(yv * sil);
        }
    }
}

// ================= launch =================
extern "C" void kernel_launch(void* const* d_in, const int* in_sizes, int n_in,
                              void* d_out, int out_size)
{
    const float* u          = (const float*)d_in[0];
    const float* in_proj_w  = (const float*)d_in[1];
    const float* z_bias     = (const float*)d_in[2];
    const float* conv_w     = (const float*)d_in[3];
    const float* conv_b     = (const float*)d_in[4];
    const float* Dparam     = (const float*)d_in[5];
    const float* out_proj_w = (const float*)d_in[6];
    float* out = (float*)d_out;

    void *p_proj = nullptr, *p_yz = nullptr, *p_ua = nullptr, *p_wa = nullptr, *p_wo = nullptr;
    cudaGetSymbolAddress(&p_proj, g_proj);
    cudaGetSymbolAddress(&p_yz, g_yz16);
    cudaGetSymbolAddress(&p_ua, g_ua16);
    cudaGetSymbolAddress(&p_wa, g_wa16);
    cudaGetSymbolAddress(&p_wo, g_wo16);

    cudaFuncSetAttribute(gemm_h, cudaFuncAttributeMaxDynamicSharedMemorySize, SMEM_GEMM);
    cudaFuncSetAttribute(states_kernel, cudaFuncAttributeMaxDynamicSharedMemorySize, SMEM_STATES);
    cudaFuncSetAttribute(y_kernel, cudaFuncAttributeMaxDynamicSharedMemorySize, SMEM_Y);

    // 0) f32 -> f16 operand conversion
    f2h_kernel<<<(NTOK * DMODEL / 2 + 255) / 256, 256>>>(u, (__half*)p_ua, NTOK * DMODEL / 2);
    f2h_kernel<<<(DPROJ * DMODEL / 2 + 255) / 256, 256>>>(in_proj_w, (__half*)p_wa, DPROJ * DMODEL / 2);
    f2h_kernel<<<(DMODEL * DINNER / 2 + 255) / 256, 256>>>(out_proj_w, (__half*)p_wo, DMODEL * DINNER / 2);

    // 1) in_proj GEMM (fp16 mma.sync): [8192,1024] x [8224,1024]^T
    {
        dim3 grid((DPROJ + 255) / 256, NTOK / 128);
        gemm_h<<<grid, 256, SMEM_GEMM>>>((const __half*)p_ua, (const __half*)p_wa,
                                         (float*)p_proj, NTOK, DPROJ, DMODEL);
    }
    // 2) conv + silu
    {
        dim3 grid(DXBC / 256, NTOK / 16);
        conv_silu_kernel<<<grid, 256>>>(conv_w, conv_b);
    }
    // 3) dA cumsum
    dacum_kernel<<<(BATCH * NHEADS * NCHUNK * 32 + 255) / 256, 256>>>();
    // 4) chunk states
    states_kernel<<<BATCH * NCHUNK * NHEADS, 256, SMEM_STATES>>>();
    // 5) inter-chunk scan
    scan_kernel<<<BATCH * NHEADS * 16, 256>>>();
    // 6) fused Y + gating (emits fp16 yz)
    y_kernel<<<BATCH * NCHUNK * NHEADS, 256, SMEM_Y>>>(z_bias, Dparam);
    // 7) out_proj GEMM (fp16 mma.sync): [8192,2048] x [1024,2048]^T
    {
        dim3 grid(DMODEL / 256, NTOK / 128);
        gemm_h<<<grid, 256, SMEM_GEMM>>>((const __half*)p_yz, (const __half*)p_wo,
                                         out, NTOK, DMODEL, DINNER);
    }
}